// round 15
// baseline (speedup 1.0000x reference)
#include <cuda_runtime.h>
#include <cuda_fp16.h>
#include <cstdint>

// Problem constants
#define Tt    1024
#define Bb    8
#define Ee    1024
#define Hh    16
#define Dh    64
#define QKVF  3072           // 3*E
#define MROWS 8192           // T*B

// Scratch (device globals — no runtime allocation allowed)
__device__ __half g_xh  [(size_t)MROWS * Ee];    // query, fp16
__device__ __half g_w1h [(size_t)QKVF * Ee];     // qkv_w, fp16
__device__ __half g_w2h [(size_t)Ee * Ee];       // out_w, fp16
__device__ __half g_qkvh[(size_t)MROWS * QKVF];  // qkv proj out (Q pre-scaled), fp16
__device__ __half g_atth[(size_t)MROWS * Ee];    // attention out, fp16
// Sync state (zero-initialized; reset by launch-B finalizer each run)
__device__ int    g_work;                        // conversion chunk claim counter
__device__ int    g_pw1;                         // W1 chunks completed (target 768)
__device__ int    g1q[64];                       // query chunks completed per m-tile (target 32)
__device__ int    g_cnt[16];                     // per-qt flash completion counters
__device__ int    g2done;                        // GEMM2 tiles completed (target 512)

// ---------------------------------------------------------------------------
// Helpers
// ---------------------------------------------------------------------------
__device__ __forceinline__ uint32_t packh2(float lo, float hi) {
    __half2 h = __floats2half2_rn(lo, hi);
    return *reinterpret_cast<uint32_t*>(&h);
}

__device__ __forceinline__ void mma16(float* c,
                                      uint32_t a0, uint32_t a1, uint32_t a2, uint32_t a3,
                                      uint32_t b0, uint32_t b1) {
    asm volatile("mma.sync.aligned.m16n8k16.row.col.f32.f16.f16.f32 "
                 "{%0,%1,%2,%3}, {%4,%5,%6,%7}, {%8,%9}, {%0,%1,%2,%3};"
                 : "+f"(c[0]), "+f"(c[1]), "+f"(c[2]), "+f"(c[3])
                 : "r"(a0), "r"(a1), "r"(a2), "r"(a3), "r"(b0), "r"(b1));
}

__device__ __forceinline__ void ldsm4(uint32_t& r0, uint32_t& r1, uint32_t& r2, uint32_t& r3,
                                      uint32_t addr) {
    asm volatile("ldmatrix.sync.aligned.m8n8.x4.shared.b16 {%0,%1,%2,%3}, [%4];"
                 : "=r"(r0), "=r"(r1), "=r"(r2), "=r"(r3) : "r"(addr));
}

__device__ __forceinline__ void ldsm4t(uint32_t& r0, uint32_t& r1, uint32_t& r2, uint32_t& r3,
                                       uint32_t addr) {
    asm volatile("ldmatrix.sync.aligned.m8n8.x4.trans.shared.b16 {%0,%1,%2,%3}, [%4];"
                 : "=r"(r0), "=r"(r1), "=r"(r2), "=r"(r3) : "r"(addr));
}

__device__ __forceinline__ void spin_until(const int* p, int target) {
    int v;
    do {
        asm volatile("ld.acquire.gpu.global.s32 %0, [%1];" : "=r"(v) : "l"(p) : "memory");
        if (v < target) __nanosleep(128);
    } while (v < target);
}

// ---------------------------------------------------------------------------
// GEMM tiling constants (R7 proven config)
// ---------------------------------------------------------------------------
#define BM   128
#define BN   128
#define BKH  32
#define NSG  4
#define ABY  (BM * 64)
#define BBY  (BN * 64)
#define STG  (ABY + BBY)        // 16384
#define GSM  (NSG * STG)        // 65536

// Conversion chunks: 1024 float4s (16KB fp32 -> 8KB fp16) each.
// Order: W1 [0,768), query [768,2816), W2 [2816,3072).
#define NCH_W1 768
#define NCH_Q  2048
#define NCH_W2 256
#define NPRE   (NCH_W1 + NCH_Q + NCH_W2)   // 3072

// ---------------------------------------------------------------------------
// Launch A: cooperative fp32->fp16 conversion + GEMM1.
// All 1536 CTAs first drain the conversion chunk queue (work-stealing —
// resident CTAs make unconditional progress, so no slot-squatting deadlock),
// then each runs its GEMM1 tile after acquire-waiting on W1 + its query rows.
// ---------------------------------------------------------------------------
__global__ void __launch_bounds__(128, 2) gemm1_fused(
    const float* __restrict__ qf, const float* __restrict__ w1f,
    const float* __restrict__ w2f, const float* __restrict__ qkv_b)
{
    extern __shared__ char smem[];
    __shared__ int s_claim;
    const uint32_t sb = (uint32_t)__cvta_generic_to_shared(smem);
    const int tid  = threadIdx.x;
    const int lane = tid & 31;
    const int warp = tid >> 5;
    const int bid  = blockIdx.x;

    // ---- Phase 1: cooperative conversion ----
    for (;;) {
        if (tid == 0) s_claim = atomicAdd(&g_work, 1);
        __syncthreads();
        const int c = s_claim;
        if (c >= NPRE) break;

        const float4* src;
        uint2* dst;
        if (c < NCH_W1) {
            src = (const float4*)w1f + (size_t)c * 1024;
            dst = (uint2*)g_w1h + (size_t)c * 1024;
        } else if (c < NCH_W1 + NCH_Q) {
            const int qc = c - NCH_W1;
            src = (const float4*)qf + (size_t)qc * 1024;
            dst = (uint2*)g_xh + (size_t)qc * 1024;
        } else {
            const int wc = c - NCH_W1 - NCH_Q;
            src = (const float4*)w2f + (size_t)wc * 1024;
            dst = (uint2*)g_w2h + (size_t)wc * 1024;
        }
        #pragma unroll
        for (int it = 0; it < 8; it++) {
            const int j = it * 128 + tid;
            float4 v = src[j];
            uint2 o;
            o.x = packh2(v.x, v.y);
            o.y = packh2(v.z, v.w);
            dst[j] = o;
        }
        __threadfence();
        __syncthreads();
        if (tid == 0) {
            if (c < NCH_W1)               atomicAdd(&g_pw1, 1);
            else if (c < NCH_W1 + NCH_Q)  atomicAdd(&g1q[(c - NCH_W1) >> 5], 1);
            // W2 chunks: no waiter inside this launch (launch B runs after)
        }
        __syncthreads();
    }

    // ---- Phase 2: GEMM1 tile (m-major: early token rows first) ----
    const int m_tile = bid / 24;
    const int n_tile = bid % 24;
    const int m0 = m_tile * BM;
    const int n0 = n_tile * BN;
    const int N = QKVF, K = Ee;

    if (tid == 0) {
        spin_until(&g_pw1, NCH_W1);
        spin_until(&g1q[m_tile], 32);
    }
    __syncthreads();

    const __half* Ah = g_xh;
    const __half* Bh = g_w1h;

    float acc[4][8][4];
    #pragma unroll
    for (int mt = 0; mt < 4; mt++)
        #pragma unroll
        for (int nt = 0; nt < 8; nt++)
            #pragma unroll
            for (int i = 0; i < 4; i++) acc[mt][nt][i] = 0.0f;

    auto load_stage = [&](int s, int c) {
        const uint32_t base = sb + s * STG;
        const int k0 = c * BKH;
        #pragma unroll
        for (int i = 0; i < 8; i++) {
            int q = tid + i * 128;
            uint32_t dst;
            const __half* src;
            if (q < 512) {
                int r = q >> 2, ch = q & 3;
                src = Ah + (size_t)(m0 + r) * K + k0 + ch * 8;
                dst = base + r * 64 + ((ch ^ ((r >> 1) & 3)) << 4);
            } else {
                int q2 = q - 512;
                int r = q2 >> 2, ch = q2 & 3;
                src = Bh + (size_t)(n0 + r) * K + k0 + ch * 8;
                dst = base + ABY + r * 64 + ((ch ^ ((r >> 1) & 3)) << 4);
            }
            asm volatile("cp.async.cg.shared.global [%0], [%1], 16;" :: "r"(dst), "l"(src));
        }
        asm volatile("cp.async.commit_group;" ::: "memory");
    };

    const int nk = K / BKH;
    load_stage(0, 0);
    load_stage(1, 1);
    load_stage(2, 2);

    const int a_rl = ((lane >> 3) & 1) * 8 + (lane & 7);
    const int a_ck = lane >> 4;
    const int b_rl = ((lane >> 4) & 1) * 8 + (lane & 7);
    const int b_ck = (lane >> 3) & 1;
    const int wm = warp & 1;
    const int wn = warp >> 1;

    uint32_t aoff[2][4], boff[2][4];
    #pragma unroll
    for (int ks = 0; ks < 2; ks++) {
        #pragma unroll
        for (int mt = 0; mt < 4; mt++) {
            int ar = wm * 64 + mt * 16 + a_rl;
            int ch = (2 * ks + a_ck) ^ ((ar >> 1) & 3);
            aoff[ks][mt] = ar * 64 + (ch << 4);
        }
        #pragma unroll
        for (int p = 0; p < 4; p++) {
            int br = wn * 64 + p * 16 + b_rl;
            int ch = (2 * ks + b_ck) ^ ((br >> 1) & 3);
            boff[ks][p] = ABY + br * 64 + (ch << 4);
        }
    }

    for (int c = 0; c < nk; c++) {
        const int s = c & (NSG - 1);
        if (c < nk - 1) asm volatile("cp.async.wait_group 2;" ::: "memory");
        else            asm volatile("cp.async.wait_group 0;" ::: "memory");
        __syncthreads();
        if (c + NSG - 1 < nk) load_stage((c + NSG - 1) & (NSG - 1), c + NSG - 1);

        const uint32_t base = sb + s * STG;
        #pragma unroll
        for (int ks = 0; ks < 2; ks++) {
            uint32_t af[4][4], bf[8][2];
            #pragma unroll
            for (int mt = 0; mt < 4; mt++)
                ldsm4(af[mt][0], af[mt][1], af[mt][2], af[mt][3], base + aoff[ks][mt]);
            #pragma unroll
            for (int p = 0; p < 4; p++) {
                uint32_t r0, r1, r2, r3;
                ldsm4(r0, r1, r2, r3, base + boff[ks][p]);
                bf[2 * p][0] = r0;     bf[2 * p][1] = r1;
                bf[2 * p + 1][0] = r2; bf[2 * p + 1][1] = r3;
            }
            #pragma unroll
            for (int mt = 0; mt < 4; mt++)
                #pragma unroll
                for (int nt = 0; nt < 8; nt++)
                    mma16(acc[mt][nt], af[mt][0], af[mt][1], af[mt][2], af[mt][3],
                          bf[nt][0], bf[nt][1]);
        }
    }

    const float scale = (n0 < Ee) ? 0.125f : 1.0f;   // Q block scaled
    const int g = lane >> 2, t = lane & 3;
    #pragma unroll
    for (int mt = 0; mt < 4; mt++) {
        const int r0 = m0 + wm * 64 + mt * 16 + g;
        #pragma unroll
        for (int nt = 0; nt < 8; nt++) {
            const int col = n0 + wn * 64 + nt * 8 + 2 * t;
            const float b0 = qkv_b[col], b1 = qkv_b[col + 1];
            *(uint32_t*)&g_qkvh[(size_t)r0 * N + col] =
                packh2((acc[mt][nt][0] + b0) * scale, (acc[mt][nt][1] + b1) * scale);
            *(uint32_t*)&g_qkvh[(size_t)(r0 + 8) * N + col] =
                packh2((acc[mt][nt][2] + b0) * scale, (acc[mt][nt][3] + b1) * scale);
        }
    }
}

// ---------------------------------------------------------------------------
// Launch B: FUSED flash + GEMM2 (proven R13) + counter-reset finalizer.
// bids [0, 2048): flash (R7 double-buffer), natural qt order, release g_cnt.
// bids [2048, 2560): GEMM2 tiles; acquire-spin g_cnt[m_tile>>2]==128.
// Last GEMM2 CTA resets all sync state for the next graph replay.
// ---------------------------------------------------------------------------
#define NFLASH 2048
#define FSTG   16384   // per-stage: K 8KB + V 8KB

__global__ void __launch_bounds__(128) flash_gemm2(
    const float* __restrict__ out_b, float* __restrict__ out)
{
    extern __shared__ char smem[];
    const uint32_t sb = (uint32_t)__cvta_generic_to_shared(smem);
    const int tid  = threadIdx.x;
    const int lane = tid & 31;
    const int g    = lane >> 2;
    const int t    = lane & 3;
    const int w    = tid >> 5;
    const int bid  = blockIdx.x;

    if (bid < NFLASH) {
        // ================= FLASH path (R7 double-buffer) =================
        const int qt = bid >> 7;
        const int bh = bid & 127;
        const int b  = bh >> 4;
        const int h  = bh & 15;
        const int q0 = qt * 64;

        uint32_t qa[4][4];
        {
            const __half* qlo = g_qkvh + ((size_t)(q0 + w * 16 + g) * Bb + b) * QKVF + h * Dh;
            const __half* qhi = qlo + (size_t)8 * Bb * QKVF;
            #pragma unroll
            for (int ks = 0; ks < 4; ks++) {
                qa[ks][0] = *(const uint32_t*)(qlo + ks * 16 + 2 * t);
                qa[ks][1] = *(const uint32_t*)(qhi + ks * 16 + 2 * t);
                qa[ks][2] = *(const uint32_t*)(qlo + ks * 16 + 8 + 2 * t);
                qa[ks][3] = *(const uint32_t*)(qhi + ks * 16 + 8 + 2 * t);
            }
        }

        auto load_kv = [&](int st, int kt) {
            const uint32_t base = sb + st * FSTG;
            const int k0 = kt * 64;
            #pragma unroll
            for (int i = 0; i < 8; i++) {
                int q = tid + i * 128;
                int off, s, c;
                uint32_t dstb;
                if (q < 512) { s = q >> 3; c = q & 7; off = Ee;     dstb = base; }
                else { int q2 = q - 512; s = q2 >> 3; c = q2 & 7; off = 2 * Ee; dstb = base + 8192; }
                const __half* src = g_qkvh + ((size_t)(k0 + s) * Bb + b) * QKVF + off + h * Dh + c * 8;
                uint32_t dst = dstb + s * 128 + ((c ^ (s & 7)) << 4);
                asm volatile("cp.async.cg.shared.global [%0], [%1], 16;" :: "r"(dst), "l"(src));
            }
            asm volatile("cp.async.commit_group;" ::: "memory");
        };

        load_kv(0, 0);

        float o[8][4];
        #pragma unroll
        for (int nt = 0; nt < 8; nt++)
            #pragma unroll
            for (int i = 0; i < 4; i++) o[nt][i] = 0.0f;
        float m0v = -1e30f, m1v = -1e30f, l0 = 0.0f, l1 = 0.0f;

        const int krl = ((lane >> 4) & 1) * 8 + (lane & 7);
        const int kck = (lane >> 3) & 1;
        const int vrl = ((lane >> 3) & 1) * 8 + (lane & 7);
        const int vck = lane >> 4;

        for (int kt = 0; kt <= qt; kt++) {
            asm volatile("cp.async.wait_group 0;" ::: "memory");
            __syncthreads();
            if (kt < qt) load_kv((kt + 1) & 1, kt + 1);

            const uint32_t Kb = sb + (kt & 1) * FSTG;
            const uint32_t Vb = Kb + 8192;

            float sv[8][4];
            #pragma unroll
            for (int nt = 0; nt < 8; nt++)
                #pragma unroll
                for (int i = 0; i < 4; i++) sv[nt][i] = 0.0f;

            #pragma unroll
            for (int ks = 0; ks < 4; ks++) {
                #pragma unroll
                for (int p = 0; p < 4; p++) {
                    int n = p * 16 + krl;
                    int ch = (2 * ks + kck) ^ (n & 7);
                    uint32_t r0, r1, r2, r3;
                    ldsm4(r0, r1, r2, r3, Kb + n * 128 + (ch << 4));
                    mma16(sv[2 * p],     qa[ks][0], qa[ks][1], qa[ks][2], qa[ks][3], r0, r1);
                    mma16(sv[2 * p + 1], qa[ks][0], qa[ks][1], qa[ks][2], qa[ks][3], r2, r3);
                }
            }

            if (kt == qt) {
                const int r_lo = w * 16 + g, r_hi = r_lo + 8;
                #pragma unroll
                for (int nt = 0; nt < 8; nt++) {
                    const int c0 = nt * 8 + 2 * t, c1 = c0 + 1;
                    if (c0 > r_lo) sv[nt][0] = -1e30f;
                    if (c1 > r_lo) sv[nt][1] = -1e30f;
                    if (c0 > r_hi) sv[nt][2] = -1e30f;
                    if (c1 > r_hi) sv[nt][3] = -1e30f;
                }
            }

            float mx0 = -1e30f, mx1 = -1e30f;
            #pragma unroll
            for (int nt = 0; nt < 8; nt++) {
                mx0 = fmaxf(mx0, fmaxf(sv[nt][0], sv[nt][1]));
                mx1 = fmaxf(mx1, fmaxf(sv[nt][2], sv[nt][3]));
            }
            mx0 = fmaxf(mx0, __shfl_xor_sync(0xffffffffu, mx0, 1));
            mx0 = fmaxf(mx0, __shfl_xor_sync(0xffffffffu, mx0, 2));
            mx1 = fmaxf(mx1, __shfl_xor_sync(0xffffffffu, mx1, 1));
            mx1 = fmaxf(mx1, __shfl_xor_sync(0xffffffffu, mx1, 2));

            const float mn0 = fmaxf(m0v, mx0), mn1 = fmaxf(m1v, mx1);
            const float al0 = __expf(m0v - mn0), al1 = __expf(m1v - mn1);
            m0v = mn0; m1v = mn1;

            float sum0 = 0.0f, sum1 = 0.0f;
            #pragma unroll
            for (int nt = 0; nt < 8; nt++) {
                sv[nt][0] = __expf(sv[nt][0] - mn0); sum0 += sv[nt][0];
                sv[nt][1] = __expf(sv[nt][1] - mn0); sum0 += sv[nt][1];
                sv[nt][2] = __expf(sv[nt][2] - mn1); sum1 += sv[nt][2];
                sv[nt][3] = __expf(sv[nt][3] - mn1); sum1 += sv[nt][3];
            }
            sum0 += __shfl_xor_sync(0xffffffffu, sum0, 1);
            sum0 += __shfl_xor_sync(0xffffffffu, sum0, 2);
            sum1 += __shfl_xor_sync(0xffffffffu, sum1, 1);
            sum1 += __shfl_xor_sync(0xffffffffu, sum1, 2);
            l0 = l0 * al0 + sum0;
            l1 = l1 * al1 + sum1;

            #pragma unroll
            for (int nt = 0; nt < 8; nt++) {
                o[nt][0] *= al0; o[nt][1] *= al0;
                o[nt][2] *= al1; o[nt][3] *= al1;
            }

            #pragma unroll
            for (int ks = 0; ks < 4; ks++) {
                const uint32_t p0 = packh2(sv[2 * ks][0],     sv[2 * ks][1]);
                const uint32_t p1 = packh2(sv[2 * ks][2],     sv[2 * ks][3]);
                const uint32_t p2 = packh2(sv[2 * ks + 1][0], sv[2 * ks + 1][1]);
                const uint32_t p3 = packh2(sv[2 * ks + 1][2], sv[2 * ks + 1][3]);
                #pragma unroll
                for (int p = 0; p < 4; p++) {
                    int srow = ks * 16 + vrl;
                    int ch = (2 * p + vck) ^ (srow & 7);
                    uint32_t r0, r1, r2, r3;
                    ldsm4t(r0, r1, r2, r3, Vb + srow * 128 + (ch << 4));
                    mma16(o[2 * p],     p0, p1, p2, p3, r0, r1);
                    mma16(o[2 * p + 1], p0, p1, p2, p3, r2, r3);
                }
            }
        }

        const float inv0 = 1.0f / l0, inv1 = 1.0f / l1;
        __half* dlo = g_atth + ((size_t)(q0 + w * 16 + g) * Bb + b) * Ee + h * Dh;
        __half* dhi = dlo + (size_t)8 * Bb * Ee;
        #pragma unroll
        for (int nt = 0; nt < 8; nt++) {
            const int c = nt * 8 + 2 * t;
            *(uint32_t*)&dlo[c] = packh2(o[nt][0] * inv0, o[nt][1] * inv0);
            *(uint32_t*)&dhi[c] = packh2(o[nt][2] * inv1, o[nt][3] * inv1);
        }

        __threadfence();
        __syncthreads();
        if (tid == 0) atomicAdd(&g_cnt[qt], 1);
        return;
    }

    // ================= GEMM2 path =================
    {
        const int t2 = bid - NFLASH;            // 0..511
        const int m_tile = t2 >> 3;
        const int n_tile = t2 & 7;
        const int m0 = m_tile * BM;
        const int n0 = n_tile * BN;

        if (tid == 0) spin_until(&g_cnt[m_tile >> 2], 128);
        __syncthreads();

        const __half* Ah = g_atth;
        const __half* Bh = g_w2h;
        const int wm = w & 1;
        const int wn = w >> 1;
        const int K = Ee, N = Ee;

        float acc[4][8][4];
        #pragma unroll
        for (int mt = 0; mt < 4; mt++)
            #pragma unroll
            for (int nt = 0; nt < 8; nt++)
                #pragma unroll
                for (int i = 0; i < 4; i++) acc[mt][nt][i] = 0.0f;

        auto load_stage = [&](int s, int c) {
            const uint32_t base = sb + s * STG;
            const int k0 = c * BKH;
            #pragma unroll
            for (int i = 0; i < 8; i++) {
                int q = tid + i * 128;
                uint32_t dst;
                const __half* src;
                if (q < 512) {
                    int r = q >> 2, ch = q & 3;
                    src = Ah + (size_t)(m0 + r) * K + k0 + ch * 8;
                    dst = base + r * 64 + ((ch ^ ((r >> 1) & 3)) << 4);
                } else {
                    int q2 = q - 512;
                    int r = q2 >> 2, ch = q2 & 3;
                    src = Bh + (size_t)(n0 + r) * K + k0 + ch * 8;
                    dst = base + ABY + r * 64 + ((ch ^ ((r >> 1) & 3)) << 4);
                }
                asm volatile("cp.async.cg.shared.global [%0], [%1], 16;" :: "r"(dst), "l"(src));
            }
            asm volatile("cp.async.commit_group;" ::: "memory");
        };

        const int nk = K / BKH;
        load_stage(0, 0);
        load_stage(1, 1);
        load_stage(2, 2);

        const int a_rl = ((lane >> 3) & 1) * 8 + (lane & 7);
        const int a_ck = lane >> 4;
        const int b_rl = ((lane >> 4) & 1) * 8 + (lane & 7);
        const int b_ck = (lane >> 3) & 1;

        uint32_t aoff[2][4], boff[2][4];
        #pragma unroll
        for (int ks = 0; ks < 2; ks++) {
            #pragma unroll
            for (int mt = 0; mt < 4; mt++) {
                int ar = wm * 64 + mt * 16 + a_rl;
                int ch = (2 * ks + a_ck) ^ ((ar >> 1) & 3);
                aoff[ks][mt] = ar * 64 + (ch << 4);
            }
            #pragma unroll
            for (int p = 0; p < 4; p++) {
                int br = wn * 64 + p * 16 + b_rl;
                int ch = (2 * ks + b_ck) ^ ((br >> 1) & 3);
                boff[ks][p] = ABY + br * 64 + (ch << 4);
            }
        }

        for (int c = 0; c < nk; c++) {
            const int s = c & (NSG - 1);
            if (c < nk - 1) asm volatile("cp.async.wait_group 2;" ::: "memory");
            else            asm volatile("cp.async.wait_group 0;" ::: "memory");
            __syncthreads();
            if (c + NSG - 1 < nk) load_stage((c + NSG - 1) & (NSG - 1), c + NSG - 1);

            const uint32_t base = sb + s * STG;
            #pragma unroll
            for (int ks = 0; ks < 2; ks++) {
                uint32_t af[4][4], bf[8][2];
                #pragma unroll
                for (int mt = 0; mt < 4; mt++)
                    ldsm4(af[mt][0], af[mt][1], af[mt][2], af[mt][3], base + aoff[ks][mt]);
                #pragma unroll
                for (int p = 0; p < 4; p++) {
                    uint32_t r0, r1, r2, r3;
                    ldsm4(r0, r1, r2, r3, base + boff[ks][p]);
                    bf[2 * p][0] = r0;     bf[2 * p][1] = r1;
                    bf[2 * p + 1][0] = r2; bf[2 * p + 1][1] = r3;
                }
                #pragma unroll
                for (int mt = 0; mt < 4; mt++)
                    #pragma unroll
                    for (int nt = 0; nt < 8; nt++)
                        mma16(acc[mt][nt], af[mt][0], af[mt][1], af[mt][2], af[mt][3],
                              bf[nt][0], bf[nt][1]);
            }
        }

        const int g2 = lane >> 2, t3 = lane & 3;
        #pragma unroll
        for (int mt = 0; mt < 4; mt++) {
            const int r0 = m0 + wm * 64 + mt * 16 + g2;
            #pragma unroll
            for (int nt = 0; nt < 8; nt++) {
                const int col = n0 + wn * 64 + nt * 8 + 2 * t3;
                const float b0 = out_b[col], b1 = out_b[col + 1];
                *(float2*)&out[(size_t)r0 * N + col] =
                    make_float2(acc[mt][nt][0] + b0, acc[mt][nt][1] + b1);
                *(float2*)&out[(size_t)(r0 + 8) * N + col] =
                    make_float2(acc[mt][nt][2] + b0, acc[mt][nt][3] + b1);
            }
        }

        // Finalizer: last GEMM2 CTA resets all sync state for next replay.
        __threadfence();
        __syncthreads();
        if (tid == 0) {
            int d = atomicAdd(&g2done, 1);
            if (d == 511) {
                #pragma unroll
                for (int i = 0; i < 16; i++) atomicExch(&g_cnt[i], 0);
                #pragma unroll
                for (int i = 0; i < 64; i++) atomicExch(&g1q[i], 0);
                atomicExch(&g_pw1, 0);
                atomicExch(&g_work, 0);
                atomicExch(&g2done, 0);
            }
        }
    }
}

// ---------------------------------------------------------------------------
// Launch
// ---------------------------------------------------------------------------
extern "C" void kernel_launch(void* const* d_in, const int* in_sizes, int n_in,
                              void* d_out, int out_size)
{
    const float* query = (const float*)d_in[0];
    const float* qkv_w = (const float*)d_in[1];
    const float* qkv_b = (const float*)d_in[2];
    const float* out_w = (const float*)d_in[3];
    const float* out_b = (const float*)d_in[4];
    float* out = (float*)d_out;

    cudaFuncSetAttribute(gemm1_fused, cudaFuncAttributeMaxDynamicSharedMemorySize, GSM);
    cudaFuncSetAttribute(flash_gemm2, cudaFuncAttributeMaxDynamicSharedMemorySize, GSM);

    // A) cooperative fp32->fp16 conversion + QKV projection (Q pre-scaled)
    gemm1_fused<<<(MROWS / BM) * (QKVF / BN), 128, GSM>>>(query, qkv_w, out_w, qkv_b);

    // B) fused causal flash attention + output projection (+ state reset)
    flash_gemm2<<<NFLASH + (MROWS / BM) * (Ee / BN), 128, GSM>>>(out_b, out);
}

// round 16
// speedup vs baseline: 1.2574x; 1.2574x over previous
#include <cuda_runtime.h>
#include <cuda_fp16.h>
#include <cstdint>

// Problem constants
#define Tt    1024
#define Bb    8
#define Ee    1024
#define Hh    16
#define Dh    64
#define QKVF  3072           // 3*E
#define MROWS 8192           // T*B

// Scratch (device globals — no runtime allocation allowed)
__device__ __half g_xh  [(size_t)MROWS * Ee];    // query, fp16
__device__ __half g_w1h [(size_t)QKVF * Ee];     // qkv_w, fp16
__device__ __half g_w2h [(size_t)Ee * Ee];       // out_w, fp16
__device__ __half g_qkvh[(size_t)MROWS * QKVF];  // qkv proj out (Q pre-scaled), fp16
__device__ __half g_atth[(size_t)MROWS * Ee];    // attention out, fp16
__device__ int    g_cnt[16];                     // per-qt flash completion counters

// ---------------------------------------------------------------------------
// Helpers
// ---------------------------------------------------------------------------
__device__ __forceinline__ uint32_t packh2(float lo, float hi) {
    __half2 h = __floats2half2_rn(lo, hi);
    return *reinterpret_cast<uint32_t*>(&h);
}

__device__ __forceinline__ void mma16(float* c,
                                      uint32_t a0, uint32_t a1, uint32_t a2, uint32_t a3,
                                      uint32_t b0, uint32_t b1) {
    asm volatile("mma.sync.aligned.m16n8k16.row.col.f32.f16.f16.f32 "
                 "{%0,%1,%2,%3}, {%4,%5,%6,%7}, {%8,%9}, {%0,%1,%2,%3};"
                 : "+f"(c[0]), "+f"(c[1]), "+f"(c[2]), "+f"(c[3])
                 : "r"(a0), "r"(a1), "r"(a2), "r"(a3), "r"(b0), "r"(b1));
}

__device__ __forceinline__ void ldsm4(uint32_t& r0, uint32_t& r1, uint32_t& r2, uint32_t& r3,
                                      uint32_t addr) {
    asm volatile("ldmatrix.sync.aligned.m8n8.x4.shared.b16 {%0,%1,%2,%3}, [%4];"
                 : "=r"(r0), "=r"(r1), "=r"(r2), "=r"(r3) : "r"(addr));
}

__device__ __forceinline__ void ldsm4t(uint32_t& r0, uint32_t& r1, uint32_t& r2, uint32_t& r3,
                                       uint32_t addr) {
    asm volatile("ldmatrix.sync.aligned.m8n8.x4.trans.shared.b16 {%0,%1,%2,%3}, [%4];"
                 : "=r"(r0), "=r"(r1), "=r"(r2), "=r"(r3) : "r"(addr));
}

// ---------------------------------------------------------------------------
// Fused prepass: fp32->fp16 for query/qkv_w/out_w, reset counters (R13).
// ---------------------------------------------------------------------------
#define NQ4  (MROWS * Ee / 4)
#define NW14 (QKVF * Ee / 4)
#define NW24 (Ee * Ee / 4)

__global__ void prepass(const float4* __restrict__ q,  const float4* __restrict__ w1,
                        const float4* __restrict__ w2,
                        uint2* __restrict__ xh, uint2* __restrict__ w1h,
                        uint2* __restrict__ w2h)
{
    int i = blockIdx.x * blockDim.x + threadIdx.x;
    if (i < 16) g_cnt[i] = 0;
    float4 v; uint2* dst;
    if (i < NQ4)                    { v = q[i];                 dst = &xh[i]; }
    else if (i < NQ4 + NW14)        { v = w1[i - NQ4];          dst = &w1h[i - NQ4]; }
    else if (i < NQ4 + NW14 + NW24) { v = w2[i - NQ4 - NW14];   dst = &w2h[i - NQ4 - NW14]; }
    else return;
    uint2 o;
    o.x = packh2(v.x, v.y);
    o.y = packh2(v.z, v.w);
    *dst = o;
}

// ---------------------------------------------------------------------------
// fp16 tensor-core GEMM (NT) — proven R7 config (used for GEMM1).
// CTA 128x128, 4 warps (2m x 2n), warp tile 64x64, BK=32, 4-stage cp.async.
// ---------------------------------------------------------------------------
#define BM   128
#define BN   128
#define BKH  32
#define NSG  4
#define ABY  (BM * 64)          // 8192
#define BBY  (BN * 64)          // 8192
#define STG  (ABY + BBY)        // 16384
#define GSM  (NSG * STG)        // 65536

__global__ void __launch_bounds__(128, 2) gemm_f16(
    const __half* __restrict__ Ah, const __half* __restrict__ Bh,
    const float* __restrict__ bias, __half* __restrict__ Ch,
    int M, int N, int K, int qscale)
{
    extern __shared__ char smem[];
    const uint32_t sb = (uint32_t)__cvta_generic_to_shared(smem);
    const int tid  = threadIdx.x;
    const int lane = tid & 31;
    const int warp = tid >> 5;
    const int wm = warp & 1;
    const int wn = warp >> 1;
    const int m0 = blockIdx.y * BM;
    const int n0 = blockIdx.x * BN;

    float acc[4][8][4];
    #pragma unroll
    for (int mt = 0; mt < 4; mt++)
        #pragma unroll
        for (int nt = 0; nt < 8; nt++)
            #pragma unroll
            for (int i = 0; i < 4; i++) acc[mt][nt][i] = 0.0f;

    auto load_stage = [&](int s, int c) {
        const uint32_t base = sb + s * STG;
        const int k0 = c * BKH;
        #pragma unroll
        for (int i = 0; i < 8; i++) {
            int q = tid + i * 128;
            uint32_t dst;
            const __half* src;
            if (q < 512) {
                int r = q >> 2, ch = q & 3;
                src = Ah + (size_t)(m0 + r) * K + k0 + ch * 8;
                dst = base + r * 64 + ((ch ^ ((r >> 1) & 3)) << 4);
            } else {
                int q2 = q - 512;
                int r = q2 >> 2, ch = q2 & 3;
                src = Bh + (size_t)(n0 + r) * K + k0 + ch * 8;
                dst = base + ABY + r * 64 + ((ch ^ ((r >> 1) & 3)) << 4);
            }
            asm volatile("cp.async.cg.shared.global [%0], [%1], 16;" :: "r"(dst), "l"(src));
        }
        asm volatile("cp.async.commit_group;" ::: "memory");
    };

    const int nk = K / BKH;
    load_stage(0, 0);
    load_stage(1, 1);
    load_stage(2, 2);

    const int a_rl = ((lane >> 3) & 1) * 8 + (lane & 7);
    const int a_ck = lane >> 4;
    const int b_rl = ((lane >> 4) & 1) * 8 + (lane & 7);
    const int b_ck = (lane >> 3) & 1;

    uint32_t aoff[2][4], boff[2][4];
    #pragma unroll
    for (int ks = 0; ks < 2; ks++) {
        #pragma unroll
        for (int mt = 0; mt < 4; mt++) {
            int ar = wm * 64 + mt * 16 + a_rl;
            int ch = (2 * ks + a_ck) ^ ((ar >> 1) & 3);
            aoff[ks][mt] = ar * 64 + (ch << 4);
        }
        #pragma unroll
        for (int p = 0; p < 4; p++) {
            int br = wn * 64 + p * 16 + b_rl;
            int ch = (2 * ks + b_ck) ^ ((br >> 1) & 3);
            boff[ks][p] = ABY + br * 64 + (ch << 4);
        }
    }

    for (int c = 0; c < nk; c++) {
        const int s = c & (NSG - 1);
        if (c < nk - 1) asm volatile("cp.async.wait_group 2;" ::: "memory");
        else            asm volatile("cp.async.wait_group 0;" ::: "memory");
        __syncthreads();
        if (c + NSG - 1 < nk) load_stage((c + NSG - 1) & (NSG - 1), c + NSG - 1);

        const uint32_t base = sb + s * STG;
        #pragma unroll
        for (int ks = 0; ks < 2; ks++) {
            uint32_t af[4][4], bf[8][2];
            #pragma unroll
            for (int mt = 0; mt < 4; mt++)
                ldsm4(af[mt][0], af[mt][1], af[mt][2], af[mt][3], base + aoff[ks][mt]);
            #pragma unroll
            for (int p = 0; p < 4; p++) {
                uint32_t r0, r1, r2, r3;
                ldsm4(r0, r1, r2, r3, base + boff[ks][p]);
                bf[2 * p][0] = r0;     bf[2 * p][1] = r1;
                bf[2 * p + 1][0] = r2; bf[2 * p + 1][1] = r3;
            }
            #pragma unroll
            for (int mt = 0; mt < 4; mt++)
                #pragma unroll
                for (int nt = 0; nt < 8; nt++)
                    mma16(acc[mt][nt], af[mt][0], af[mt][1], af[mt][2], af[mt][3],
                          bf[nt][0], bf[nt][1]);
        }
    }

    const float scale = (qscale && n0 < Ee) ? 0.125f : 1.0f;
    const int g = lane >> 2, t = lane & 3;
    #pragma unroll
    for (int mt = 0; mt < 4; mt++) {
        const int r0 = m0 + wm * 64 + mt * 16 + g;
        #pragma unroll
        for (int nt = 0; nt < 8; nt++) {
            const int col = n0 + wn * 64 + nt * 8 + 2 * t;
            const float b0 = bias[col], b1 = bias[col + 1];
            *(uint32_t*)&Ch[(size_t)r0 * N + col] =
                packh2((acc[mt][nt][0] + b0) * scale, (acc[mt][nt][1] + b1) * scale);
            *(uint32_t*)&Ch[(size_t)(r0 + 8) * N + col] =
                packh2((acc[mt][nt][2] + b0) * scale, (acc[mt][nt][3] + b1) * scale);
        }
    }
}

// ---------------------------------------------------------------------------
// FUSED flash + GEMM2 kernel (R13 protocol).
// Flash now uses a 4-stage cp.async pipeline in the already-allocated 64KB
// dynamic smem, with EXACT waits:
//   prologue issues min(3,nkt) tiles; at iter kt, pending = issued - kt,
//   wait_group (pending-1); post-barrier load targets stage (kt-1)&3 whose
//   readers all finished before this iteration's barrier.
// ---------------------------------------------------------------------------
#define NFLASH 2048
#define FSTG   16384   // per-stage: K 8KB + V 8KB (4 stages = 64KB = GSM)

__global__ void __launch_bounds__(128) flash_gemm2(
    const float* __restrict__ out_b, float* __restrict__ out)
{
    extern __shared__ char smem[];
    const uint32_t sb = (uint32_t)__cvta_generic_to_shared(smem);
    const int tid  = threadIdx.x;
    const int lane = tid & 31;
    const int g    = lane >> 2;
    const int t    = lane & 3;
    const int w    = tid >> 5;
    const int bid  = blockIdx.x;

    if (bid < NFLASH) {
        // ================= FLASH path (4-stage pipeline) =================
        const int qt = bid >> 7;        // natural order: light first
        const int bh = bid & 127;
        const int b  = bh >> 4;
        const int h  = bh & 15;
        const int q0 = qt * 64;

        uint32_t qa[4][4];
        {
            const __half* qlo = g_qkvh + ((size_t)(q0 + w * 16 + g) * Bb + b) * QKVF + h * Dh;
            const __half* qhi = qlo + (size_t)8 * Bb * QKVF;
            #pragma unroll
            for (int ks = 0; ks < 4; ks++) {
                qa[ks][0] = *(const uint32_t*)(qlo + ks * 16 + 2 * t);
                qa[ks][1] = *(const uint32_t*)(qhi + ks * 16 + 2 * t);
                qa[ks][2] = *(const uint32_t*)(qlo + ks * 16 + 8 + 2 * t);
                qa[ks][3] = *(const uint32_t*)(qhi + ks * 16 + 8 + 2 * t);
            }
        }

        auto load_kv = [&](int st, int kt) {
            const uint32_t base = sb + st * FSTG;
            const int k0 = kt * 64;
            #pragma unroll
            for (int i = 0; i < 8; i++) {
                int q = tid + i * 128;
                int off, s, c;
                uint32_t dstb;
                if (q < 512) { s = q >> 3; c = q & 7; off = Ee;     dstb = base; }
                else { int q2 = q - 512; s = q2 >> 3; c = q2 & 7; off = 2 * Ee; dstb = base + 8192; }
                const __half* src = g_qkvh + ((size_t)(k0 + s) * Bb + b) * QKVF + off + h * Dh + c * 8;
                uint32_t dst = dstb + s * 128 + ((c ^ (s & 7)) << 4);
                asm volatile("cp.async.cg.shared.global [%0], [%1], 16;" :: "r"(dst), "l"(src));
            }
            asm volatile("cp.async.commit_group;" ::: "memory");
        };

        const int nkt = qt + 1;
        int issued = 0;
        #pragma unroll
        for (int j = 0; j < 3; j++)
            if (j < nkt) { load_kv(j & 3, j); issued++; }

        float o[8][4];
        #pragma unroll
        for (int nt = 0; nt < 8; nt++)
            #pragma unroll
            for (int i = 0; i < 4; i++) o[nt][i] = 0.0f;
        float m0v = -1e30f, m1v = -1e30f, l0 = 0.0f, l1 = 0.0f;

        const int krl = ((lane >> 4) & 1) * 8 + (lane & 7);
        const int kck = (lane >> 3) & 1;
        const int vrl = ((lane >> 3) & 1) * 8 + (lane & 7);
        const int vck = lane >> 4;

        for (int kt = 0; kt < nkt; kt++) {
            // Exact wait for tile kt: pending = issued - kt groups outstanding;
            // need all but (pending-1) most recent complete.
            const int pending = issued - kt;
            if (pending >= 3)      asm volatile("cp.async.wait_group 2;" ::: "memory");
            else if (pending == 2) asm volatile("cp.async.wait_group 1;" ::: "memory");
            else                   asm volatile("cp.async.wait_group 0;" ::: "memory");
            __syncthreads();
            if (issued < nkt) { load_kv(issued & 3, issued); issued++; }

            const uint32_t Kb = sb + (kt & 3) * FSTG;
            const uint32_t Vb = Kb + 8192;

            float sv[8][4];
            #pragma unroll
            for (int nt = 0; nt < 8; nt++)
                #pragma unroll
                for (int i = 0; i < 4; i++) sv[nt][i] = 0.0f;

            #pragma unroll
            for (int ks = 0; ks < 4; ks++) {
                #pragma unroll
                for (int p = 0; p < 4; p++) {
                    int n = p * 16 + krl;
                    int ch = (2 * ks + kck) ^ (n & 7);
                    uint32_t r0, r1, r2, r3;
                    ldsm4(r0, r1, r2, r3, Kb + n * 128 + (ch << 4));
                    mma16(sv[2 * p],     qa[ks][0], qa[ks][1], qa[ks][2], qa[ks][3], r0, r1);
                    mma16(sv[2 * p + 1], qa[ks][0], qa[ks][1], qa[ks][2], qa[ks][3], r2, r3);
                }
            }

            if (kt == qt) {
                const int r_lo = w * 16 + g, r_hi = r_lo + 8;
                #pragma unroll
                for (int nt = 0; nt < 8; nt++) {
                    const int c0 = nt * 8 + 2 * t, c1 = c0 + 1;
                    if (c0 > r_lo) sv[nt][0] = -1e30f;
                    if (c1 > r_lo) sv[nt][1] = -1e30f;
                    if (c0 > r_hi) sv[nt][2] = -1e30f;
                    if (c1 > r_hi) sv[nt][3] = -1e30f;
                }
            }

            float mx0 = -1e30f, mx1 = -1e30f;
            #pragma unroll
            for (int nt = 0; nt < 8; nt++) {
                mx0 = fmaxf(mx0, fmaxf(sv[nt][0], sv[nt][1]));
                mx1 = fmaxf(mx1, fmaxf(sv[nt][2], sv[nt][3]));
            }
            mx0 = fmaxf(mx0, __shfl_xor_sync(0xffffffffu, mx0, 1));
            mx0 = fmaxf(mx0, __shfl_xor_sync(0xffffffffu, mx0, 2));
            mx1 = fmaxf(mx1, __shfl_xor_sync(0xffffffffu, mx1, 1));
            mx1 = fmaxf(mx1, __shfl_xor_sync(0xffffffffu, mx1, 2));

            const float mn0 = fmaxf(m0v, mx0), mn1 = fmaxf(m1v, mx1);
            const float al0 = __expf(m0v - mn0), al1 = __expf(m1v - mn1);
            m0v = mn0; m1v = mn1;

            float sum0 = 0.0f, sum1 = 0.0f;
            #pragma unroll
            for (int nt = 0; nt < 8; nt++) {
                sv[nt][0] = __expf(sv[nt][0] - mn0); sum0 += sv[nt][0];
                sv[nt][1] = __expf(sv[nt][1] - mn0); sum0 += sv[nt][1];
                sv[nt][2] = __expf(sv[nt][2] - mn1); sum1 += sv[nt][2];
                sv[nt][3] = __expf(sv[nt][3] - mn1); sum1 += sv[nt][3];
            }
            sum0 += __shfl_xor_sync(0xffffffffu, sum0, 1);
            sum0 += __shfl_xor_sync(0xffffffffu, sum0, 2);
            sum1 += __shfl_xor_sync(0xffffffffu, sum1, 1);
            sum1 += __shfl_xor_sync(0xffffffffu, sum1, 2);
            l0 = l0 * al0 + sum0;
            l1 = l1 * al1 + sum1;

            #pragma unroll
            for (int nt = 0; nt < 8; nt++) {
                o[nt][0] *= al0; o[nt][1] *= al0;
                o[nt][2] *= al1; o[nt][3] *= al1;
            }

            #pragma unroll
            for (int ks = 0; ks < 4; ks++) {
                const uint32_t p0 = packh2(sv[2 * ks][0],     sv[2 * ks][1]);
                const uint32_t p1 = packh2(sv[2 * ks][2],     sv[2 * ks][3]);
                const uint32_t p2 = packh2(sv[2 * ks + 1][0], sv[2 * ks + 1][1]);
                const uint32_t p3 = packh2(sv[2 * ks + 1][2], sv[2 * ks + 1][3]);
                #pragma unroll
                for (int p = 0; p < 4; p++) {
                    int srow = ks * 16 + vrl;
                    int ch = (2 * p + vck) ^ (srow & 7);
                    uint32_t r0, r1, r2, r3;
                    ldsm4t(r0, r1, r2, r3, Vb + srow * 128 + (ch << 4));
                    mma16(o[2 * p],     p0, p1, p2, p3, r0, r1);
                    mma16(o[2 * p + 1], p0, p1, p2, p3, r2, r3);
                }
            }
        }

        const float inv0 = 1.0f / l0, inv1 = 1.0f / l1;
        __half* dlo = g_atth + ((size_t)(q0 + w * 16 + g) * Bb + b) * Ee + h * Dh;
        __half* dhi = dlo + (size_t)8 * Bb * Ee;
        #pragma unroll
        for (int nt = 0; nt < 8; nt++) {
            const int c = nt * 8 + 2 * t;
            *(uint32_t*)&dlo[c] = packh2(o[nt][0] * inv0, o[nt][1] * inv0);
            *(uint32_t*)&dhi[c] = packh2(o[nt][2] * inv1, o[nt][3] * inv1);
        }

        // Publish completion (release)
        __threadfence();
        __syncthreads();
        if (tid == 0) atomicAdd(&g_cnt[qt], 1);
        return;
    }

    // ================= GEMM2 path (unchanged R13) =================
    {
        const int t2 = bid - NFLASH;            // 0..511, early tokens first
        const int m_tile = t2 >> 3;
        const int n_tile = t2 & 7;
        const int m0 = m_tile * BM;
        const int n0 = n_tile * BN;
        const int qw = m_tile >> 2;

        if (tid == 0) {
            int v;
            do {
                asm volatile("ld.acquire.gpu.global.s32 %0, [%1];"
                             : "=r"(v) : "l"(&g_cnt[qw]) : "memory");
                if (v < 128) __nanosleep(256);
            } while (v < 128);
        }
        __syncthreads();

        const __half* Ah = g_atth;
        const __half* Bh = g_w2h;
        const int wm = w & 1;
        const int wn = w >> 1;
        const int K = Ee, N = Ee;

        float acc[4][8][4];
        #pragma unroll
        for (int mt = 0; mt < 4; mt++)
            #pragma unroll
            for (int nt = 0; nt < 8; nt++)
                #pragma unroll
                for (int i = 0; i < 4; i++) acc[mt][nt][i] = 0.0f;

        auto load_stage = [&](int s, int c) {
            const uint32_t base = sb + s * STG;
            const int k0 = c * BKH;
            #pragma unroll
            for (int i = 0; i < 8; i++) {
                int q = tid + i * 128;
                uint32_t dst;
                const __half* src;
                if (q < 512) {
                    int r = q >> 2, ch = q & 3;
                    src = Ah + (size_t)(m0 + r) * K + k0 + ch * 8;
                    dst = base + r * 64 + ((ch ^ ((r >> 1) & 3)) << 4);
                } else {
                    int q2 = q - 512;
                    int r = q2 >> 2, ch = q2 & 3;
                    src = Bh + (size_t)(n0 + r) * K + k0 + ch * 8;
                    dst = base + ABY + r * 64 + ((ch ^ ((r >> 1) & 3)) << 4);
                }
                asm volatile("cp.async.cg.shared.global [%0], [%1], 16;" :: "r"(dst), "l"(src));
            }
            asm volatile("cp.async.commit_group;" ::: "memory");
        };

        const int nk = K / BKH;
        load_stage(0, 0);
        load_stage(1, 1);
        load_stage(2, 2);

        const int a_rl = ((lane >> 3) & 1) * 8 + (lane & 7);
        const int a_ck = lane >> 4;
        const int b_rl = ((lane >> 4) & 1) * 8 + (lane & 7);
        const int b_ck = (lane >> 3) & 1;

        uint32_t aoff[2][4], boff[2][4];
        #pragma unroll
        for (int ks = 0; ks < 2; ks++) {
            #pragma unroll
            for (int mt = 0; mt < 4; mt++) {
                int ar = wm * 64 + mt * 16 + a_rl;
                int ch = (2 * ks + a_ck) ^ ((ar >> 1) & 3);
                aoff[ks][mt] = ar * 64 + (ch << 4);
            }
            #pragma unroll
            for (int p = 0; p < 4; p++) {
                int br = wn * 64 + p * 16 + b_rl;
                int ch = (2 * ks + b_ck) ^ ((br >> 1) & 3);
                boff[ks][p] = ABY + br * 64 + (ch << 4);
            }
        }

        for (int c = 0; c < nk; c++) {
            const int s = c & (NSG - 1);
            if (c < nk - 1) asm volatile("cp.async.wait_group 2;" ::: "memory");
            else            asm volatile("cp.async.wait_group 0;" ::: "memory");
            __syncthreads();
            if (c + NSG - 1 < nk) load_stage((c + NSG - 1) & (NSG - 1), c + NSG - 1);

            const uint32_t base = sb + s * STG;
            #pragma unroll
            for (int ks = 0; ks < 2; ks++) {
                uint32_t af[4][4], bf[8][2];
                #pragma unroll
                for (int mt = 0; mt < 4; mt++)
                    ldsm4(af[mt][0], af[mt][1], af[mt][2], af[mt][3], base + aoff[ks][mt]);
                #pragma unroll
                for (int p = 0; p < 4; p++) {
                    uint32_t r0, r1, r2, r3;
                    ldsm4(r0, r1, r2, r3, base + boff[ks][p]);
                    bf[2 * p][0] = r0;     bf[2 * p][1] = r1;
                    bf[2 * p + 1][0] = r2; bf[2 * p + 1][1] = r3;
                }
                #pragma unroll
                for (int mt = 0; mt < 4; mt++)
                    #pragma unroll
                    for (int nt = 0; nt < 8; nt++)
                        mma16(acc[mt][nt], af[mt][0], af[mt][1], af[mt][2], af[mt][3],
                              bf[nt][0], bf[nt][1]);
            }
        }

        const int g2 = lane >> 2, t3 = lane & 3;
        #pragma unroll
        for (int mt = 0; mt < 4; mt++) {
            const int r0 = m0 + wm * 64 + mt * 16 + g2;
            #pragma unroll
            for (int nt = 0; nt < 8; nt++) {
                const int col = n0 + wn * 64 + nt * 8 + 2 * t3;
                const float b0 = out_b[col], b1 = out_b[col + 1];
                *(float2*)&out[(size_t)r0 * N + col] =
                    make_float2(acc[mt][nt][0] + b0, acc[mt][nt][1] + b1);
                *(float2*)&out[(size_t)(r0 + 8) * N + col] =
                    make_float2(acc[mt][nt][2] + b0, acc[mt][nt][3] + b1);
            }
        }
    }
}

// ---------------------------------------------------------------------------
// Launch
// ---------------------------------------------------------------------------
extern "C" void kernel_launch(void* const* d_in, const int* in_sizes, int n_in,
                              void* d_out, int out_size)
{
    const float* query = (const float*)d_in[0];
    const float* qkv_w = (const float*)d_in[1];
    const float* qkv_b = (const float*)d_in[2];
    const float* out_w = (const float*)d_in[3];
    const float* out_b = (const float*)d_in[4];
    float* out = (float*)d_out;

    void *p_xh = nullptr, *p_w1h = nullptr, *p_w2h = nullptr, *p_qkvh = nullptr;
    cudaGetSymbolAddress(&p_xh,   g_xh);
    cudaGetSymbolAddress(&p_w1h,  g_w1h);
    cudaGetSymbolAddress(&p_w2h,  g_w2h);
    cudaGetSymbolAddress(&p_qkvh, g_qkvh);

    cudaFuncSetAttribute(gemm_f16,    cudaFuncAttributeMaxDynamicSharedMemorySize, GSM);
    cudaFuncSetAttribute(flash_gemm2, cudaFuncAttributeMaxDynamicSharedMemorySize, GSM);

    // 0) fused prepass: fp32->fp16 conversions + counter resets
    const int ntot4 = NQ4 + NW14 + NW24;
    prepass<<<(ntot4 + 255) / 256, 256>>>(
        (const float4*)query, (const float4*)qkv_w, (const float4*)out_w,
        (uint2*)p_xh, (uint2*)p_w1h, (uint2*)p_w2h);

    // 1) QKV projection -> fp16, Q block scaled by 0.125 (proven R7 GEMM)
    gemm_f16<<<dim3(QKVF / BN, MROWS / BM), 128, GSM>>>(
        (const __half*)p_xh, (const __half*)p_w1h, qkv_b,
        (__half*)p_qkvh, MROWS, QKVF, Ee, 1);

    // 2+3) Fused causal flash attention + output projection
    flash_gemm2<<<NFLASH + (MROWS / BM) * (Ee / BN), 128, GSM>>>(out_b, out);
}

// round 17
// speedup vs baseline: 1.2994x; 1.0334x over previous
#include <cuda_runtime.h>
#include <cuda_fp16.h>
#include <cstdint>

// Problem constants
#define Tt    1024
#define Bb    8
#define Ee    1024
#define Hh    16
#define Dh    64
#define QKVF  3072           // 3*E
#define MROWS 8192           // T*B

// Scratch (device globals — no runtime allocation allowed)
__device__ __half g_xh  [(size_t)MROWS * Ee];    // query, fp16
__device__ __half g_w1h [(size_t)QKVF * Ee];     // qkv_w, fp16
__device__ __half g_w2h [(size_t)Ee * Ee];       // out_w, fp16
__device__ __half g_qkvh[(size_t)MROWS * QKVF];  // qkv proj out (Q pre-scaled), fp16
__device__ __half g_atth[(size_t)MROWS * Ee];    // attention out, fp16
__device__ int    g_cnt[16];                     // per-qt flash completion counters

// ---------------------------------------------------------------------------
// Helpers
// ---------------------------------------------------------------------------
__device__ __forceinline__ uint32_t packh2(float lo, float hi) {
    __half2 h = __floats2half2_rn(lo, hi);
    return *reinterpret_cast<uint32_t*>(&h);
}

__device__ __forceinline__ void mma16(float* c,
                                      uint32_t a0, uint32_t a1, uint32_t a2, uint32_t a3,
                                      uint32_t b0, uint32_t b1) {
    asm volatile("mma.sync.aligned.m16n8k16.row.col.f32.f16.f16.f32 "
                 "{%0,%1,%2,%3}, {%4,%5,%6,%7}, {%8,%9}, {%0,%1,%2,%3};"
                 : "+f"(c[0]), "+f"(c[1]), "+f"(c[2]), "+f"(c[3])
                 : "r"(a0), "r"(a1), "r"(a2), "r"(a3), "r"(b0), "r"(b1));
}

__device__ __forceinline__ void ldsm4(uint32_t& r0, uint32_t& r1, uint32_t& r2, uint32_t& r3,
                                      uint32_t addr) {
    asm volatile("ldmatrix.sync.aligned.m8n8.x4.shared.b16 {%0,%1,%2,%3}, [%4];"
                 : "=r"(r0), "=r"(r1), "=r"(r2), "=r"(r3) : "r"(addr));
}

__device__ __forceinline__ void ldsm4t(uint32_t& r0, uint32_t& r1, uint32_t& r2, uint32_t& r3,
                                       uint32_t addr) {
    asm volatile("ldmatrix.sync.aligned.m8n8.x4.trans.shared.b16 {%0,%1,%2,%3}, [%4];"
                 : "=r"(r0), "=r"(r1), "=r"(r2), "=r"(r3) : "r"(addr));
}

// ---------------------------------------------------------------------------
// Fused prepass: fp32->fp16 for query/qkv_w/out_w, reset counters.
// ---------------------------------------------------------------------------
#define NQ4  (MROWS * Ee / 4)
#define NW14 (QKVF * Ee / 4)
#define NW24 (Ee * Ee / 4)

__global__ void prepass(const float4* __restrict__ q,  const float4* __restrict__ w1,
                        const float4* __restrict__ w2,
                        uint2* __restrict__ xh, uint2* __restrict__ w1h,
                        uint2* __restrict__ w2h)
{
    int i = blockIdx.x * blockDim.x + threadIdx.x;
    if (i < 16) g_cnt[i] = 0;
    float4 v; uint2* dst;
    if (i < NQ4)                    { v = q[i];                 dst = &xh[i]; }
    else if (i < NQ4 + NW14)        { v = w1[i - NQ4];          dst = &w1h[i - NQ4]; }
    else if (i < NQ4 + NW14 + NW24) { v = w2[i - NQ4 - NW14];   dst = &w2h[i - NQ4 - NW14]; }
    else return;
    uint2 o;
    o.x = packh2(v.x, v.y);
    o.y = packh2(v.z, v.w);
    *dst = o;
}

// ---------------------------------------------------------------------------
// GEMM1: fp16 tensor-core GEMM (NT), CTA tile 128x96 (wave-quantization fix:
// 2048 tiles / 296 slots = 6.92 waves -> 98.9% slot efficiency vs 86.5%).
// 4 warps (2m x 2n), warp tile 64x48, BK=32, 4-stage cp.async (14KB/stage).
// Q-scale applied PER COLUMN (tile 10 straddles the Q/K boundary at col 1024).
// ---------------------------------------------------------------------------
#define BM1   128
#define BN1   96
#define BKH   32
#define NSG   4
#define ABY1  (BM1 * 64)         // 8192
#define BBY1  (BN1 * 64)         // 6144
#define STG1  (ABY1 + BBY1)      // 14336
#define GSM1  (NSG * STG1)       // 57344

__global__ void __launch_bounds__(128, 2) gemm1_f16(
    const __half* __restrict__ Ah, const __half* __restrict__ Bh,
    const float* __restrict__ bias, __half* __restrict__ Ch,
    int M, int N, int K)
{
    extern __shared__ char smem[];
    const uint32_t sb = (uint32_t)__cvta_generic_to_shared(smem);
    const int tid  = threadIdx.x;
    const int lane = tid & 31;
    const int warp = tid >> 5;
    const int wm = warp & 1;
    const int wn = warp >> 1;
    const int m0 = blockIdx.y * BM1;
    const int n0 = blockIdx.x * BN1;

    float acc[4][6][4];
    #pragma unroll
    for (int mt = 0; mt < 4; mt++)
        #pragma unroll
        for (int nt = 0; nt < 6; nt++)
            #pragma unroll
            for (int i = 0; i < 4; i++) acc[mt][nt][i] = 0.0f;

    auto load_stage = [&](int s, int c) {
        const uint32_t base = sb + s * STG1;
        const int k0 = c * BKH;
        #pragma unroll
        for (int i = 0; i < 7; i++) {
            int q = tid + i * 128;
            uint32_t dst;
            const __half* src;
            if (q < 512) {                   // A: 128 rows x 4 chunks
                int r = q >> 2, ch = q & 3;
                src = Ah + (size_t)(m0 + r) * K + k0 + ch * 8;
                dst = base + r * 64 + ((ch ^ ((r >> 1) & 3)) << 4);
            } else {                         // B: 96 rows x 4 chunks
                int q2 = q - 512;            // 0..383
                int r = q2 >> 2, ch = q2 & 3;
                src = Bh + (size_t)(n0 + r) * K + k0 + ch * 8;
                dst = base + ABY1 + r * 64 + ((ch ^ ((r >> 1) & 3)) << 4);
            }
            asm volatile("cp.async.cg.shared.global [%0], [%1], 16;" :: "r"(dst), "l"(src));
        }
        asm volatile("cp.async.commit_group;" ::: "memory");
    };

    const int nk = K / BKH;
    load_stage(0, 0);
    load_stage(1, 1);
    load_stage(2, 2);

    const int a_rl = ((lane >> 3) & 1) * 8 + (lane & 7);
    const int a_ck = lane >> 4;
    const int b_rl = ((lane >> 4) & 1) * 8 + (lane & 7);
    const int b_ck = (lane >> 3) & 1;

    uint32_t aoff[2][4], boff[2][3];
    #pragma unroll
    for (int ks = 0; ks < 2; ks++) {
        #pragma unroll
        for (int mt = 0; mt < 4; mt++) {
            int ar = wm * 64 + mt * 16 + a_rl;
            int ch = (2 * ks + a_ck) ^ ((ar >> 1) & 3);
            aoff[ks][mt] = ar * 64 + (ch << 4);
        }
        #pragma unroll
        for (int p = 0; p < 3; p++) {
            int br = wn * 48 + p * 16 + b_rl;
            int ch = (2 * ks + b_ck) ^ ((br >> 1) & 3);
            boff[ks][p] = ABY1 + br * 64 + (ch << 4);
        }
    }

    for (int c = 0; c < nk; c++) {
        const int s = c & (NSG - 1);
        if (c < nk - 1) asm volatile("cp.async.wait_group 2;" ::: "memory");
        else            asm volatile("cp.async.wait_group 0;" ::: "memory");
        __syncthreads();
        if (c + NSG - 1 < nk) load_stage((c + NSG - 1) & (NSG - 1), c + NSG - 1);

        const uint32_t base = sb + s * STG1;
        #pragma unroll
        for (int ks = 0; ks < 2; ks++) {
            uint32_t af[4][4], bf[6][2];
            #pragma unroll
            for (int mt = 0; mt < 4; mt++)
                ldsm4(af[mt][0], af[mt][1], af[mt][2], af[mt][3], base + aoff[ks][mt]);
            #pragma unroll
            for (int p = 0; p < 3; p++) {
                uint32_t r0, r1, r2, r3;
                ldsm4(r0, r1, r2, r3, base + boff[ks][p]);
                bf[2 * p][0] = r0;     bf[2 * p][1] = r1;
                bf[2 * p + 1][0] = r2; bf[2 * p + 1][1] = r3;
            }
            #pragma unroll
            for (int mt = 0; mt < 4; mt++)
                #pragma unroll
                for (int nt = 0; nt < 6; nt++)
                    mma16(acc[mt][nt], af[mt][0], af[mt][1], af[mt][2], af[mt][3],
                          bf[nt][0], bf[nt][1]);
        }
    }

    const int g = lane >> 2, t = lane & 3;
    #pragma unroll
    for (int mt = 0; mt < 4; mt++) {
        const int r0 = m0 + wm * 64 + mt * 16 + g;
        #pragma unroll
        for (int nt = 0; nt < 6; nt++) {
            const int col = n0 + wn * 48 + nt * 8 + 2 * t;
            const float sc = (col < Ee) ? 0.125f : 1.0f;   // per-column Q scale
            const float b0 = bias[col], b1 = bias[col + 1];
            *(uint32_t*)&Ch[(size_t)r0 * N + col] =
                packh2((acc[mt][nt][0] + b0) * sc, (acc[mt][nt][1] + b1) * sc);
            *(uint32_t*)&Ch[(size_t)(r0 + 8) * N + col] =
                packh2((acc[mt][nt][2] + b0) * sc, (acc[mt][nt][3] + b1) * sc);
        }
    }
}

// ---------------------------------------------------------------------------
// FUSED flash + GEMM2 kernel (R16: 4-stage flash pipeline w/ exact waits,
// R13 dependency protocol; GEMM2 128x128 R7 loop).
// ---------------------------------------------------------------------------
#define BM   128
#define BN   128
#define ABY  (BM * 64)
#define BBY  (BN * 64)
#define STG  (ABY + BBY)        // 16384
#define GSM  (NSG * STG)        // 65536
#define NFLASH 2048
#define FSTG   16384   // per-stage: K 8KB + V 8KB (4 stages = 64KB = GSM)

__global__ void __launch_bounds__(128) flash_gemm2(
    const float* __restrict__ out_b, float* __restrict__ out)
{
    extern __shared__ char smem[];
    const uint32_t sb = (uint32_t)__cvta_generic_to_shared(smem);
    const int tid  = threadIdx.x;
    const int lane = tid & 31;
    const int g    = lane >> 2;
    const int t    = lane & 3;
    const int w    = tid >> 5;
    const int bid  = blockIdx.x;

    if (bid < NFLASH) {
        // ================= FLASH path (4-stage pipeline) =================
        const int qt = bid >> 7;
        const int bh = bid & 127;
        const int b  = bh >> 4;
        const int h  = bh & 15;
        const int q0 = qt * 64;

        uint32_t qa[4][4];
        {
            const __half* qlo = g_qkvh + ((size_t)(q0 + w * 16 + g) * Bb + b) * QKVF + h * Dh;
            const __half* qhi = qlo + (size_t)8 * Bb * QKVF;
            #pragma unroll
            for (int ks = 0; ks < 4; ks++) {
                qa[ks][0] = *(const uint32_t*)(qlo + ks * 16 + 2 * t);
                qa[ks][1] = *(const uint32_t*)(qhi + ks * 16 + 2 * t);
                qa[ks][2] = *(const uint32_t*)(qlo + ks * 16 + 8 + 2 * t);
                qa[ks][3] = *(const uint32_t*)(qhi + ks * 16 + 8 + 2 * t);
            }
        }

        auto load_kv = [&](int st, int kt) {
            const uint32_t base = sb + st * FSTG;
            const int k0 = kt * 64;
            #pragma unroll
            for (int i = 0; i < 8; i++) {
                int q = tid + i * 128;
                int off, s, c;
                uint32_t dstb;
                if (q < 512) { s = q >> 3; c = q & 7; off = Ee;     dstb = base; }
                else { int q2 = q - 512; s = q2 >> 3; c = q2 & 7; off = 2 * Ee; dstb = base + 8192; }
                const __half* src = g_qkvh + ((size_t)(k0 + s) * Bb + b) * QKVF + off + h * Dh + c * 8;
                uint32_t dst = dstb + s * 128 + ((c ^ (s & 7)) << 4);
                asm volatile("cp.async.cg.shared.global [%0], [%1], 16;" :: "r"(dst), "l"(src));
            }
            asm volatile("cp.async.commit_group;" ::: "memory");
        };

        const int nkt = qt + 1;
        int issued = 0;
        #pragma unroll
        for (int j = 0; j < 3; j++)
            if (j < nkt) { load_kv(j & 3, j); issued++; }

        float o[8][4];
        #pragma unroll
        for (int nt = 0; nt < 8; nt++)
            #pragma unroll
            for (int i = 0; i < 4; i++) o[nt][i] = 0.0f;
        float m0v = -1e30f, m1v = -1e30f, l0 = 0.0f, l1 = 0.0f;

        const int krl = ((lane >> 4) & 1) * 8 + (lane & 7);
        const int kck = (lane >> 3) & 1;
        const int vrl = ((lane >> 3) & 1) * 8 + (lane & 7);
        const int vck = lane >> 4;

        for (int kt = 0; kt < nkt; kt++) {
            const int pending = issued - kt;
            if (pending >= 3)      asm volatile("cp.async.wait_group 2;" ::: "memory");
            else if (pending == 2) asm volatile("cp.async.wait_group 1;" ::: "memory");
            else                   asm volatile("cp.async.wait_group 0;" ::: "memory");
            __syncthreads();
            if (issued < nkt) { load_kv(issued & 3, issued); issued++; }

            const uint32_t Kb = sb + (kt & 3) * FSTG;
            const uint32_t Vb = Kb + 8192;

            float sv[8][4];
            #pragma unroll
            for (int nt = 0; nt < 8; nt++)
                #pragma unroll
                for (int i = 0; i < 4; i++) sv[nt][i] = 0.0f;

            #pragma unroll
            for (int ks = 0; ks < 4; ks++) {
                #pragma unroll
                for (int p = 0; p < 4; p++) {
                    int n = p * 16 + krl;
                    int ch = (2 * ks + kck) ^ (n & 7);
                    uint32_t r0, r1, r2, r3;
                    ldsm4(r0, r1, r2, r3, Kb + n * 128 + (ch << 4));
                    mma16(sv[2 * p],     qa[ks][0], qa[ks][1], qa[ks][2], qa[ks][3], r0, r1);
                    mma16(sv[2 * p + 1], qa[ks][0], qa[ks][1], qa[ks][2], qa[ks][3], r2, r3);
                }
            }

            if (kt == qt) {
                const int r_lo = w * 16 + g, r_hi = r_lo + 8;
                #pragma unroll
                for (int nt = 0; nt < 8; nt++) {
                    const int c0 = nt * 8 + 2 * t, c1 = c0 + 1;
                    if (c0 > r_lo) sv[nt][0] = -1e30f;
                    if (c1 > r_lo) sv[nt][1] = -1e30f;
                    if (c0 > r_hi) sv[nt][2] = -1e30f;
                    if (c1 > r_hi) sv[nt][3] = -1e30f;
                }
            }

            float mx0 = -1e30f, mx1 = -1e30f;
            #pragma unroll
            for (int nt = 0; nt < 8; nt++) {
                mx0 = fmaxf(mx0, fmaxf(sv[nt][0], sv[nt][1]));
                mx1 = fmaxf(mx1, fmaxf(sv[nt][2], sv[nt][3]));
            }
            mx0 = fmaxf(mx0, __shfl_xor_sync(0xffffffffu, mx0, 1));
            mx0 = fmaxf(mx0, __shfl_xor_sync(0xffffffffu, mx0, 2));
            mx1 = fmaxf(mx1, __shfl_xor_sync(0xffffffffu, mx1, 1));
            mx1 = fmaxf(mx1, __shfl_xor_sync(0xffffffffu, mx1, 2));

            const float mn0 = fmaxf(m0v, mx0), mn1 = fmaxf(m1v, mx1);
            const float al0 = __expf(m0v - mn0), al1 = __expf(m1v - mn1);
            m0v = mn0; m1v = mn1;

            float sum0 = 0.0f, sum1 = 0.0f;
            #pragma unroll
            for (int nt = 0; nt < 8; nt++) {
                sv[nt][0] = __expf(sv[nt][0] - mn0); sum0 += sv[nt][0];
                sv[nt][1] = __expf(sv[nt][1] - mn0); sum0 += sv[nt][1];
                sv[nt][2] = __expf(sv[nt][2] - mn1); sum1 += sv[nt][2];
                sv[nt][3] = __expf(sv[nt][3] - mn1); sum1 += sv[nt][3];
            }
            sum0 += __shfl_xor_sync(0xffffffffu, sum0, 1);
            sum0 += __shfl_xor_sync(0xffffffffu, sum0, 2);
            sum1 += __shfl_xor_sync(0xffffffffu, sum1, 1);
            sum1 += __shfl_xor_sync(0xffffffffu, sum1, 2);
            l0 = l0 * al0 + sum0;
            l1 = l1 * al1 + sum1;

            #pragma unroll
            for (int nt = 0; nt < 8; nt++) {
                o[nt][0] *= al0; o[nt][1] *= al0;
                o[nt][2] *= al1; o[nt][3] *= al1;
            }

            #pragma unroll
            for (int ks = 0; ks < 4; ks++) {
                const uint32_t p0 = packh2(sv[2 * ks][0],     sv[2 * ks][1]);
                const uint32_t p1 = packh2(sv[2 * ks][2],     sv[2 * ks][3]);
                const uint32_t p2 = packh2(sv[2 * ks + 1][0], sv[2 * ks + 1][1]);
                const uint32_t p3 = packh2(sv[2 * ks + 1][2], sv[2 * ks + 1][3]);
                #pragma unroll
                for (int p = 0; p < 4; p++) {
                    int srow = ks * 16 + vrl;
                    int ch = (2 * p + vck) ^ (srow & 7);
                    uint32_t r0, r1, r2, r3;
                    ldsm4t(r0, r1, r2, r3, Vb + srow * 128 + (ch << 4));
                    mma16(o[2 * p],     p0, p1, p2, p3, r0, r1);
                    mma16(o[2 * p + 1], p0, p1, p2, p3, r2, r3);
                }
            }
        }

        const float inv0 = 1.0f / l0, inv1 = 1.0f / l1;
        __half* dlo = g_atth + ((size_t)(q0 + w * 16 + g) * Bb + b) * Ee + h * Dh;
        __half* dhi = dlo + (size_t)8 * Bb * Ee;
        #pragma unroll
        for (int nt = 0; nt < 8; nt++) {
            const int c = nt * 8 + 2 * t;
            *(uint32_t*)&dlo[c] = packh2(o[nt][0] * inv0, o[nt][1] * inv0);
            *(uint32_t*)&dhi[c] = packh2(o[nt][2] * inv1, o[nt][3] * inv1);
        }

        __threadfence();
        __syncthreads();
        if (tid == 0) atomicAdd(&g_cnt[qt], 1);
        return;
    }

    // ================= GEMM2 path (unchanged R13) =================
    {
        const int t2 = bid - NFLASH;
        const int m_tile = t2 >> 3;
        const int n_tile = t2 & 7;
        const int m0 = m_tile * BM;
        const int n0 = n_tile * BN;
        const int qw = m_tile >> 2;

        if (tid == 0) {
            int v;
            do {
                asm volatile("ld.acquire.gpu.global.s32 %0, [%1];"
                             : "=r"(v) : "l"(&g_cnt[qw]) : "memory");
                if (v < 128) __nanosleep(256);
            } while (v < 128);
        }
        __syncthreads();

        const __half* Ah = g_atth;
        const __half* Bh = g_w2h;
        const int wm = w & 1;
        const int wn = w >> 1;
        const int K = Ee, N = Ee;

        float acc[4][8][4];
        #pragma unroll
        for (int mt = 0; mt < 4; mt++)
            #pragma unroll
            for (int nt = 0; nt < 8; nt++)
                #pragma unroll
                for (int i = 0; i < 4; i++) acc[mt][nt][i] = 0.0f;

        auto load_stage = [&](int s, int c) {
            const uint32_t base = sb + s * STG;
            const int k0 = c * BKH;
            #pragma unroll
            for (int i = 0; i < 8; i++) {
                int q = tid + i * 128;
                uint32_t dst;
                const __half* src;
                if (q < 512) {
                    int r = q >> 2, ch = q & 3;
                    src = Ah + (size_t)(m0 + r) * K + k0 + ch * 8;
                    dst = base + r * 64 + ((ch ^ ((r >> 1) & 3)) << 4);
                } else {
                    int q2 = q - 512;
                    int r = q2 >> 2, ch = q2 & 3;
                    src = Bh + (size_t)(n0 + r) * K + k0 + ch * 8;
                    dst = base + ABY + r * 64 + ((ch ^ ((r >> 1) & 3)) << 4);
                }
                asm volatile("cp.async.cg.shared.global [%0], [%1], 16;" :: "r"(dst), "l"(src));
            }
            asm volatile("cp.async.commit_group;" ::: "memory");
        };

        const int nk = K / BKH;
        load_stage(0, 0);
        load_stage(1, 1);
        load_stage(2, 2);

        const int a_rl = ((lane >> 3) & 1) * 8 + (lane & 7);
        const int a_ck = lane >> 4;
        const int b_rl = ((lane >> 4) & 1) * 8 + (lane & 7);
        const int b_ck = (lane >> 3) & 1;

        uint32_t aoff[2][4], boff[2][4];
        #pragma unroll
        for (int ks = 0; ks < 2; ks++) {
            #pragma unroll
            for (int mt = 0; mt < 4; mt++) {
                int ar = wm * 64 + mt * 16 + a_rl;
                int ch = (2 * ks + a_ck) ^ ((ar >> 1) & 3);
                aoff[ks][mt] = ar * 64 + (ch << 4);
            }
            #pragma unroll
            for (int p = 0; p < 4; p++) {
                int br = wn * 64 + p * 16 + b_rl;
                int ch = (2 * ks + b_ck) ^ ((br >> 1) & 3);
                boff[ks][p] = ABY + br * 64 + (ch << 4);
            }
        }

        for (int c = 0; c < nk; c++) {
            const int s = c & (NSG - 1);
            if (c < nk - 1) asm volatile("cp.async.wait_group 2;" ::: "memory");
            else            asm volatile("cp.async.wait_group 0;" ::: "memory");
            __syncthreads();
            if (c + NSG - 1 < nk) load_stage((c + NSG - 1) & (NSG - 1), c + NSG - 1);

            const uint32_t base = sb + s * STG;
            #pragma unroll
            for (int ks = 0; ks < 2; ks++) {
                uint32_t af[4][4], bf[8][2];
                #pragma unroll
                for (int mt = 0; mt < 4; mt++)
                    ldsm4(af[mt][0], af[mt][1], af[mt][2], af[mt][3], base + aoff[ks][mt]);
                #pragma unroll
                for (int p = 0; p < 4; p++) {
                    uint32_t r0, r1, r2, r3;
                    ldsm4(r0, r1, r2, r3, base + boff[ks][p]);
                    bf[2 * p][0] = r0;     bf[2 * p][1] = r1;
                    bf[2 * p + 1][0] = r2; bf[2 * p + 1][1] = r3;
                }
                #pragma unroll
                for (int mt = 0; mt < 4; mt++)
                    #pragma unroll
                    for (int nt = 0; nt < 8; nt++)
                        mma16(acc[mt][nt], af[mt][0], af[mt][1], af[mt][2], af[mt][3],
                              bf[nt][0], bf[nt][1]);
            }
        }

        const int g2 = lane >> 2, t3 = lane & 3;
        #pragma unroll
        for (int mt = 0; mt < 4; mt++) {
            const int r0 = m0 + wm * 64 + mt * 16 + g2;
            #pragma unroll
            for (int nt = 0; nt < 8; nt++) {
                const int col = n0 + wn * 64 + nt * 8 + 2 * t3;
                const float b0 = out_b[col], b1 = out_b[col + 1];
                *(float2*)&out[(size_t)r0 * N + col] =
                    make_float2(acc[mt][nt][0] + b0, acc[mt][nt][1] + b1);
                *(float2*)&out[(size_t)(r0 + 8) * N + col] =
                    make_float2(acc[mt][nt][2] + b0, acc[mt][nt][3] + b1);
            }
        }
    }
}

// ---------------------------------------------------------------------------
// Launch
// ---------------------------------------------------------------------------
extern "C" void kernel_launch(void* const* d_in, const int* in_sizes, int n_in,
                              void* d_out, int out_size)
{
    const float* query = (const float*)d_in[0];
    const float* qkv_w = (const float*)d_in[1];
    const float* qkv_b = (const float*)d_in[2];
    const float* out_w = (const float*)d_in[3];
    const float* out_b = (const float*)d_in[4];
    float* out = (float*)d_out;

    void *p_xh = nullptr, *p_w1h = nullptr, *p_w2h = nullptr, *p_qkvh = nullptr;
    cudaGetSymbolAddress(&p_xh,   g_xh);
    cudaGetSymbolAddress(&p_w1h,  g_w1h);
    cudaGetSymbolAddress(&p_w2h,  g_w2h);
    cudaGetSymbolAddress(&p_qkvh, g_qkvh);

    cudaFuncSetAttribute(gemm1_f16,   cudaFuncAttributeMaxDynamicSharedMemorySize, GSM1);
    cudaFuncSetAttribute(flash_gemm2, cudaFuncAttributeMaxDynamicSharedMemorySize, GSM);

    // 0) fused prepass: fp32->fp16 conversions + counter resets
    const int ntot4 = NQ4 + NW14 + NW24;
    prepass<<<(ntot4 + 255) / 256, 256>>>(
        (const float4*)query, (const float4*)qkv_w, (const float4*)out_w,
        (uint2*)p_xh, (uint2*)p_w1h, (uint2*)p_w2h);

    // 1) QKV projection -> fp16, Q columns scaled by 0.125 (128x96 tiles)
    gemm1_f16<<<dim3(QKVF / BN1, MROWS / BM1), 128, GSM1>>>(
        (const __half*)p_xh, (const __half*)p_w1h, qkv_b,
        (__half*)p_qkvh, MROWS, QKVF, Ee);

    // 2+3) Fused causal flash attention + output projection
    flash_gemm2<<<NFLASH + (MROWS / BM) * (Ee / BN), 128, GSM>>>(out_b, out);
}